// round 10
// baseline (speedup 1.0000x reference)
#include <cuda_runtime.h>

// ---------------------------------------------------------------------------
// SSIM (16,3,512,512) fp32, 11x11 gaussian (sigma=1.5), zero padding.
// Round-10 (base R9 82.4us):
//  * column-interleaved (c,d) smem: slot[col] = u64(c,d). Horizontal tap =
//    ONE LDS.64 yielding the packed operand (was 2 LDS.32 + pack).
//  * race-free in-place transform: 8-byte cp.async places img1-pairs in even
//    8B slots, img2-pairs in odd slots of the same 16B group; pre-pass thread
//    reads 16B (a0,a1,b0,b1) and rewrites the SAME 16B as (c0,d0,c1,d1).
//  * math (33+22 fma/row), ring, epilogue, 7 blocks/SM all unchanged.
// ---------------------------------------------------------------------------

#define IMG_H 512
#define IMG_W 512
#define N_PLANES 48
#define N_BLOCKS (48 * 4 * 16)
#define TOTAL_PIX 12582912.0

#define GW0 0.26601172f
#define GW1 0.21300554f
#define GW2 0.10936069f
#define GW3 0.03600077f
#define GW4 0.00759876f
#define GW5 0.00102842f

__device__ double g_acc;
__device__ unsigned int g_count;

typedef unsigned long long u64;

__device__ __forceinline__ u64 pk2(float lo, float hi) {
    u64 r; asm("mov.b64 %0, {%1, %2};" : "=l"(r) : "f"(lo), "f"(hi)); return r;
}
__device__ __forceinline__ float2 upk2(u64 v) {
    float2 r; asm("mov.b64 {%0, %1}, %2;" : "=f"(r.x), "=f"(r.y) : "l"(v)); return r;
}
__device__ __forceinline__ u64 fma2(u64 a, u64 b, u64 c) {
    u64 d; asm("fma.rn.f32x2 %0, %1, %2, %3;" : "=l"(d) : "l"(a), "l"(b), "l"(c)); return d;
}
__device__ __forceinline__ u64 mul2(u64 a, u64 b) {
    u64 d; asm("mul.rn.f32x2 %0, %1, %2;" : "=l"(d) : "l"(a), "l"(b)); return d;
}
__device__ __forceinline__ void cp8(unsigned dst, const float* src, unsigned rs) {
    asm volatile("cp.async.ca.shared.global [%0], [%1], 8, %2;"
                 :: "r"(dst), "l"(src), "r"(rs));
}

// 144 u64 slots per row (one per column), global cols [col0-8, col0+136)
// thread tx's 11-tap window: slots tx+3 .. tx+13 (max 141 < 144)
#define NSLOT 144
#define ROW_B (NSLOT * 8)          // 1152 bytes
#define BUF_B (11 * ROW_B)         // 12672 bytes
#define NGRP  (NSLOT / 2)          // 72 16B groups per row

__global__ __launch_bounds__(128, 7)
void ssim_kernel(const float* __restrict__ img1, const float* __restrict__ img2,
                 float* __restrict__ out) {
    const int plane = blockIdx.x;     // 0..47
    const int strip = blockIdx.y;     // 0..3
    const int band  = blockIdx.z;     // 0..15  (row bands of 32)
    const int tx    = threadIdx.x;

    const int col0 = strip * 128;
    const int row0 = band * 32;

    const float* __restrict__ p1 = img1 + (size_t)plane * (IMG_H * IMG_W);
    const float* __restrict__ p2 = img2 + (size_t)plane * (IMG_H * IMG_W);

    // [buf][row][slot]; slot s holds (c,d) of column s after pre-pass.
    // before pre-pass: even slot = img1 pair, odd slot = img2 pair (same cols)
    __shared__ __align__(16) u64 smem[2][11][NSLOT];

    unsigned sbase;
    asm("{ .reg .u64 t; cvta.to.shared.u64 t, %1; cvt.u32.u64 %0, t; }"
        : "=r"(sbase) : "l"((const void*)smem));

    // loader: slot s covers global col pair (col0-8+(s&~1)) .. +1 from
    // img1 (s even) / img2 (s odd). thread tx owns slot tx; tx<16 also tx+128.
    const int  gb0  = col0 - 8 + (tx & ~1);
    const bool ok0  = ((unsigned)gb0 < (unsigned)IMG_W);
    const float* __restrict__ src0 = ((tx & 1) ? p2 : p1) + gb0;
    const bool has1 = (tx < NSLOT - 128);              // tx < 16
    const int  gb1  = gb0 + 128;
    const bool ok1  = has1 && ((unsigned)gb1 < (unsigned)IMG_W);
    const float* __restrict__ src1 = ((tx & 1) ? p2 : p1) + gb1;
    const unsigned ldst = sbase + (unsigned)(tx * 8);

    const u64 W2_0 = pk2(GW0, GW0), W2_1 = pk2(GW1, GW1), W2_2 = pk2(GW2, GW2);
    const u64 W2_3 = pk2(GW3, GW3), W2_4 = pk2(GW4, GW4), W2_5 = pk2(GW5, GW5);
    const u64 WT[11] = {W2_5, W2_4, W2_3, W2_2, W2_1, W2_0,
                        W2_1, W2_2, W2_3, W2_4, W2_5};
    const u64 NEG1 = pk2(-1.f, -1.f);

    u64 ring01[11], ringq[11];
#pragma unroll
    for (int k = 0; k < 11; ++k) { ring01[k] = 0ull; ringq[k] = 0ull; }

    float acc = 0.f;
    const float C1  = 1e-4f;
    const float C2  = 9e-4f;
    const float C2E = 9e-4f + 1e-6f;

    auto load_chunk = [&](int t, int bb) {
        const int base = row0 - 5 + t * 11;
        const unsigned dbase = ldst + (unsigned)(bb * BUF_B);
#pragma unroll
        for (int r = 0; r < 11; ++r) {
            const int y = base + r;
            const bool rowok = ((unsigned)y < (unsigned)IMG_H);
            const int off = y * IMG_W;
            const bool k0 = rowok && ok0;
            cp8(dbase + (unsigned)(r * ROW_B), k0 ? (src0 + off) : p1, k0 ? 8u : 0u);
            if (has1) {
                const bool k1 = rowok && ok1;
                cp8(dbase + (unsigned)(r * ROW_B + 1024),
                    k1 ? (src1 + off) : p1, k1 ? 8u : 0u);
            }
        }
        asm volatile("cp.async.commit_group;");
    };

    load_chunk(0, 0);

    // input rows n = t*11 + k, 4 chunks; outputs for n in [10, 42)
    for (int t = 0; t < 4; ++t) {
        const int cur = t & 1;
        if (t < 3) {
            load_chunk(t + 1, cur ^ 1);
            asm volatile("cp.async.wait_group 1;");
        } else {
            asm volatile("cp.async.wait_group 0;");
        }
        __syncthreads();   // chunk t raw data visible

        // pre-pass: each 16B group (a0,a1,b0,b1) -> (c0,d0,c1,d1), in place.
        // thread tx<72 owns group tx of every row: read set == write set.
        if (tx < NGRP) {
            float4* G = (float4*)(smem[cur][0]) + tx;   // group tx of row 0
#pragma unroll
            for (int r = 0; r < 11; ++r) {
                float4 v = G[r * NGRP];                 // (a0, a1, b0, b1)
                float4 o;
                o.x = v.x + v.z;   // c0
                o.y = v.x - v.z;   // d0
                o.z = v.y + v.w;   // c1
                o.w = v.y - v.w;   // d1
                G[r * NGRP] = o;
            }
        }
        __syncthreads();   // (c,d) visible to all

#pragma unroll
        for (int k = 0; k < 11; ++k) {
            const u64* srow = smem[cur][k];
            u64 h01 = 0ull, hq = 0ull;
#pragma unroll
            for (int i = 0; i < 11; ++i) {
                const u64 vv = srow[tx + 3 + i];   // LDS.64: (c,d)
                const u64 w  = WT[i];
                h01 = fma2(w, vv, h01);            // (+wc, +wd)
                const u64 p = mul2(w, vv);         // (wc, wd)
                hq  = fma2(p, vv, hq);             // (+wc^2, +wd^2)
            }
            ring01[k] = h01;
            ringq [k] = hq;

            const int n = t * 11 + k;
            if (n >= 10 && n < 42) {
                u64 m12 = 0ull, qv = 0ull;
#pragma unroll
                for (int j = 0; j < 11; ++j) {
                    const int s = (k + 1 + j) % 11;   // static after unroll
                    const u64 w = WT[j];
                    m12 = fma2(w, ring01[s], m12);    // (C, D)
                    qv  = fma2(w, ringq [s], qv);     // (Qc, Qd)
                }
                const u64 cd2 = mul2(m12, m12);           // (C^2, D^2)
                const u64 ev  = fma2(cd2, NEG1, qv);      // (Ec, Ed)
                const float2 s2 = upk2(cd2);
                const float2 e2 = upk2(ev);
                const float M = s2.x - s2.y;   // 4*mu1*mu2
                const float P = s2.x + s2.y;   // 2*(mu1^2+mu2^2)
                const float S = e2.x - e2.y;   // 4*sig12
                const float T = e2.x + e2.y;   // 2*sigpp
                const float num = fmaf(0.5f, M, C1) * fmaf(0.5f, S, C2);
                const float den = fmaf(0.5f, P, C1) * fmaf(0.5f, T, C2E);
                acc += __fdividef(num, den);
            }
        }
        __syncthreads();   // buffer cur free for chunk t+2's cp.async
    }

#pragma unroll
    for (int o = 16; o > 0; o >>= 1)
        acc += __shfl_xor_sync(0xFFFFFFFFu, acc, o);

    __shared__ float wsum[4];
    if ((tx & 31) == 0) wsum[tx >> 5] = acc;
    __syncthreads();

    if (tx == 0) {
        const float s = wsum[0] + wsum[1] + wsum[2] + wsum[3];
        atomicAdd(&g_acc, (double)s);
        __threadfence();
        const unsigned int done = atomicAdd(&g_count, 1u);
        if (done == (unsigned)(N_BLOCKS - 1)) {
            const double total = atomicAdd(&g_acc, 0.0);
            out[0] = (float)(total / TOTAL_PIX);
            g_acc = 0.0;
            g_count = 0u;
            __threadfence();
        }
    }
}

extern "C" void kernel_launch(void* const* d_in, const int* in_sizes, int n_in,
                              void* d_out, int out_size) {
    const float* img1 = (const float*)d_in[0];
    const float* img2 = (const float*)d_in[1];
    float* out = (float*)d_out;
    (void)in_sizes; (void)n_in; (void)out_size;

    dim3 grid(N_PLANES, 4, 16);
    ssim_kernel<<<grid, 128>>>(img1, img2, out);
}